// round 1
// baseline (speedup 1.0000x reference)
#include <cuda_runtime.h>
#include <cstddef>

// Problem constants (fixed shapes from reference)
#define N_ROWS 14400      // bs*Q = 16*900
#define N_CLS  91
#define N_TGT  4096
#define T_OUT  4096

#define TILE_T 256        // targets per block (128 threads x 2 targets)
#define TILE_R 32         // rows per block

// Scratch (no allocations allowed in kernel_launch)
__device__ float  g_cc[N_ROWS * N_CLS];     // focal class cost (pos - neg), 5.24 MB
__device__ float4 g_rxyxy[N_ROWS];
__device__ float  g_rarea[N_ROWS];
__device__ float4 g_txyxy[N_TGT];
__device__ float  g_tarea[N_TGT];

// ---------------------------------------------------------------------------
// Prep 1: per (row, class) focal cost table.
// p = sigmoid(x); pos = 0.25*(1-p)^2*(-log(p+eps)); neg = 0.75*p^2*(-log1p(-p+eps))
// ---------------------------------------------------------------------------
__global__ void prep_class_kernel(const float* __restrict__ logits) {
    int i = blockIdx.x * blockDim.x + threadIdx.x;
    if (i >= N_ROWS * N_CLS) return;
    float x = logits[i];
    float p = 1.0f / (1.0f + expf(-x));
    float om = 1.0f - p;
    float pos = 0.25f * om * om * (-logf(p + 1e-8f));
    float neg = 0.75f * p * p * (-log1pf(-p + 1e-8f));
    g_cc[i] = pos - neg;
}

// ---------------------------------------------------------------------------
// Prep 2: cxcywh -> xyxy + area for pred rows and targets.
// ---------------------------------------------------------------------------
__global__ void prep_boxes_kernel(const float* __restrict__ pboxes,
                                  const float* __restrict__ tboxes) {
    int i = blockIdx.x * blockDim.x + threadIdx.x;
    if (i < N_ROWS) {
        float4 b = ((const float4*)pboxes)[i];
        float x0 = b.x - 0.5f * b.z, y0 = b.y - 0.5f * b.w;
        float x1 = b.x + 0.5f * b.z, y1 = b.y + 0.5f * b.w;
        g_rxyxy[i] = make_float4(x0, y0, x1, y1);
        g_rarea[i] = (x1 - x0) * (y1 - y0);
    }
    if (i < N_TGT) {
        float4 b = ((const float4*)tboxes)[i];
        float x0 = b.x - 0.5f * b.z, y0 = b.y - 0.5f * b.w;
        float x1 = b.x + 0.5f * b.z, y1 = b.y + 0.5f * b.w;
        g_txyxy[i] = make_float4(x0, y0, x1, y1);
        g_tarea[i] = (x1 - x0) * (y1 - y0);
    }
}

// ---------------------------------------------------------------------------
// Per-pair cost
// ---------------------------------------------------------------------------
__device__ __forceinline__ float pair_cost(
    float rx0, float ry0, float rx1, float ry1, float rar,
    float rcx, float rcy, float rw, float rh,
    float4 t, float tar, float4 tc, float cc)
{
    // L1 on cxcywh
    float l1 = fabsf(rcx - tc.x) + fabsf(rcy - tc.y)
             + fabsf(rw  - tc.z) + fabsf(rh  - tc.w);
    // intersection
    float ltx = fmaxf(rx0, t.x), lty = fmaxf(ry0, t.y);
    float rbx = fminf(rx1, t.z), rby = fminf(ry1, t.w);
    float iw = fmaxf(rbx - ltx, 0.0f), ih = fmaxf(rby - lty, 0.0f);
    float inter = iw * ih;
    float uni = rar + tar - inter;
    // enclosing box
    float lex = fminf(rx0, t.x), ley = fminf(ry0, t.y);
    float rex = fmaxf(rx1, t.z), rey = fmaxf(ry1, t.w);
    float ew = fmaxf(rex - lex, 0.0f), eh = fmaxf(rey - ley, 0.0f);
    float ae = ew * eh;
    float giou = __fdividef(inter, uni) - __fdividef(ae - uni, ae);
    return 5.0f * l1 + 2.0f * cc - 2.0f * giou;
}

// ---------------------------------------------------------------------------
// Main: each block = 256 targets x 32 rows. 128 threads, 2 targets/thread.
// Lanes span targets -> coalesced float2 stores on contiguous T dimension.
// Row data staged in shared (broadcast reads). cc gather stays within a
// 364B row span -> L1 friendly.
// ---------------------------------------------------------------------------
__global__ void __launch_bounds__(128)
cost_kernel(const float* __restrict__ tboxes,
            const int*   __restrict__ tids,
            float*       __restrict__ out)
{
    __shared__ float s_row[TILE_R][9];

    const int n0 = blockIdx.y * TILE_R;
    const int t0 = blockIdx.x * TILE_T + threadIdx.x * 2;

    // Stage 32 rows x 9 floats (xyxy, area, cxcywh)
    for (int i = threadIdx.x; i < TILE_R * 9; i += 128) {
        int r = i / 9, f = i - r * 9;
        int n = n0 + r;
        float v;
        if (f < 4)       v = ((const float*)&g_rxyxy[n])[f];
        else if (f == 4) v = g_rarea[n];
        else             v = ((const float*)&g_rxyxy[0])[0]; // placeholder (overwritten below)
        if (f >= 5) {
            // cxcywh straight from the prep-free path: recompute from xyxy is
            // lossy, so fetch from global pred_boxes via g arrays is not
            // available here; instead store cxcywh in shared from xyxy inverse.
            // NOT USED — see below.
        }
        s_row[r][f] = v;
    }
    // Overwrite slots 5..8 with exact cxcywh from pred_boxes (passed via tboxes? no)
    __syncthreads();

    // -- dummy to keep structure; real staging done in second pass below --
    (void)tboxes; (void)tids; (void)out; (void)t0;
}

// NOTE: the kernel above is replaced by the real one below; kept out of use.

__global__ void __launch_bounds__(128)
cost_kernel_main(const float* __restrict__ pboxes,
                 const float* __restrict__ tboxes,
                 const int*   __restrict__ tids,
                 float*       __restrict__ out)
{
    __shared__ float s_row[TILE_R][9];

    const int n0 = blockIdx.y * TILE_R;
    const int t0 = blockIdx.x * TILE_T + threadIdx.x * 2;

    // Stage 32 rows x 9 floats: [0..3] xyxy, [4] area, [5..8] cxcywh
    for (int i = threadIdx.x; i < TILE_R * 9; i += 128) {
        int r = i / 9, f = i - r * 9;
        int n = n0 + r;
        float v;
        if (f < 4)       v = ((const float*)&g_rxyxy[n])[f];
        else if (f == 4) v = g_rarea[n];
        else             v = pboxes[n * 4 + (f - 5)];
        s_row[r][f] = v;
    }

    // Per-thread target data (2 targets) in registers
    const float4 ta = g_txyxy[t0];
    const float4 tb = g_txyxy[t0 + 1];
    const float  aa = g_tarea[t0];
    const float  ab = g_tarea[t0 + 1];
    const float4 ca = ((const float4*)tboxes)[t0];
    const float4 cb = ((const float4*)tboxes)[t0 + 1];
    const int cls0 = tids[t0];
    const int cls1 = tids[t0 + 1];

    __syncthreads();

    #pragma unroll 4
    for (int r = 0; r < TILE_R; ++r) {
        const int n = n0 + r;
        const float rx0 = s_row[r][0], ry0 = s_row[r][1];
        const float rx1 = s_row[r][2], ry1 = s_row[r][3];
        const float rar = s_row[r][4];
        const float rcx = s_row[r][5], rcy = s_row[r][6];
        const float rw  = s_row[r][7], rh  = s_row[r][8];

        const float cc0 = g_cc[n * N_CLS + cls0];
        const float cc1 = g_cc[n * N_CLS + cls1];

        float c0 = pair_cost(rx0, ry0, rx1, ry1, rar, rcx, rcy, rw, rh,
                             ta, aa, ca, cc0);
        float c1 = pair_cost(rx0, ry0, rx1, ry1, rar, rcx, rcy, rw, rh,
                             tb, ab, cb, cc1);

        *(float2*)(out + (size_t)n * T_OUT + t0) = make_float2(c0, c1);
    }
}

// ---------------------------------------------------------------------------
// Launch
// ---------------------------------------------------------------------------
extern "C" void kernel_launch(void* const* d_in, const int* in_sizes, int n_in,
                              void* d_out, int out_size) {
    const float* logits = (const float*)d_in[0];   // [16,900,91]
    const float* pboxes = (const float*)d_in[1];   // [16,900,4]
    const int*   tids   = (const int*)  d_in[2];   // [4096]
    const float* tboxes = (const float*)d_in[3];   // [4096,4]
    float*       out    = (float*)d_out;           // [16,900,4096]

    {
        int total = N_ROWS * N_CLS;
        prep_class_kernel<<<(total + 255) / 256, 256>>>(logits);
    }
    {
        int total = (N_ROWS > N_TGT ? N_ROWS : N_TGT);
        prep_boxes_kernel<<<(total + 255) / 256, 256>>>(pboxes, tboxes);
    }
    {
        dim3 grid(T_OUT / TILE_T, N_ROWS / TILE_R);
        cost_kernel_main<<<grid, 128>>>(pboxes, tboxes, tids, out);
    }
}